// round 12
// baseline (speedup 1.0000x reference)
#include <cuda_runtime.h>
#include <cstdint>

#define D    512
#define NBAT 256
#define H    128
#define LDIM 64
#define NV   32000
#define G5   640          // 5*H
#define NH   (NBAT*H)     // 32768

// ---- persistent device scratch (allocation-free rule) ----
__device__ float g_hst[D * NBAT * H];     // 64 MB
__device__ float g_cst[D * NBAT * H];     // 64 MB
__device__ float g_table[(size_t)NV * G5];// 82 MB: emb@W[0:64] + b
__device__ int   g_lidx[D * NBAT];        // left-child step index, -1 = shift

__device__ __forceinline__ float sigf(float x) {
    return __fdividef(1.0f, 1.0f + __expf(-x));
}
__device__ __forceinline__ float tanhfast(float x) {
    return 1.0f - __fdividef(2.0f, __expf(2.0f * x) + 1.0f);
}
__device__ __forceinline__ float ull_lo(unsigned long long v) {
    return __uint_as_float((unsigned)(v & 0xffffffffull));
}
__device__ __forceinline__ float ull_hi(unsigned long long v) {
    return __uint_as_float((unsigned)(v >> 32));
}

// ============================================================
// K_pre: grid (1000, 5). y<4: table tiles; y==4,x==0: lidx sim.
// ============================================================
__global__ __launch_bounds__(256) void k_pre(const float* __restrict__ emb,
                                             const float* __restrict__ W,
                                             const float* __restrict__ bias,
                                             const int* __restrict__ trans) {
    if (blockIdx.y == 4) {
        if (blockIdx.x != 0) return;
        int b = threadIdx.x;
        short st[D];
        int ptr = 0;
        for (int t = 0; t < D; t++) {
            int m = trans[t * NBAT + b];
            int lx = -1;
            if (m) lx = st[ptr - 2];
            int np = ptr - 2 * m;
            st[np] = (short)t;
            ptr = np + 1;
            g_lidx[t * NBAT + b] = lx;
        }
        return;
    }
    extern __shared__ float sm[];
    float* emb_s = sm;              // [64][33]
    float* W_sc  = sm + 64 * 33;    // [64][160]
    const int v0 = blockIdx.x * 32;
    const int c0 = blockIdx.y * 160;
    const int tid = threadIdx.x;

    for (int idx = tid; idx < 32 * 64; idx += 256) {
        int vv = idx >> 6, k = idx & 63;
        emb_s[k * 33 + vv] = emb[(v0 + vv) * LDIM + k];
    }
    for (int idx = tid; idx < 64 * 40; idx += 256) {
        int k = idx / 40, cq = idx % 40;
        float4 w4 = *reinterpret_cast<const float4*>(&W[k * G5 + c0 + cq * 4]);
        *reinterpret_cast<float4*>(&W_sc[k * 160 + cq * 4]) = w4;
    }
    __syncthreads();

    const int vg = tid & 7;
    const int cg = tid >> 3;
    float acc[4][5];
#pragma unroll
    for (int j = 0; j < 5; j++) {
        float bj = __ldg(&bias[c0 + cg * 5 + j]);
#pragma unroll
        for (int i = 0; i < 4; i++) acc[i][j] = bj;
    }
#pragma unroll 4
    for (int k = 0; k < 64; k++) {
        float x[4], w[5];
#pragma unroll
        for (int i = 0; i < 4; i++) x[i] = emb_s[k * 33 + vg * 4 + i];
#pragma unroll
        for (int j = 0; j < 5; j++) w[j] = W_sc[k * 160 + cg * 5 + j];
#pragma unroll
        for (int i = 0; i < 4; i++)
#pragma unroll
            for (int j = 0; j < 5; j++) acc[i][j] += x[i] * w[j];
    }
#pragma unroll
    for (int i = 0; i < 4; i++)
#pragma unroll
        for (int j = 0; j < 5; j++)
            g_table[(size_t)(v0 + vg * 4 + i) * G5 + c0 + cg * 5 + j] = acc[i][j];
}

// ============================================================
// Main: 32 active clusters of 4 CTAs (grid 148), 512 thr/CTA.
// R12: 4 warps/SMSP for latency hiding; tile 2b x 5g; f32 Gp;
// cp.async.wait_group before final sync (race fix).
// ============================================================
#define XK     260
#define WROW   260
#define XBUF   (8 * XK)                      // 2080 floats
#define HSROW  36
#define GPR    34                            // f32 partial row: 32 + 2 pad
#define SM_WT  0                             // 160*260 = 41600
#define SM_X   41600                         // + 4160 -> 45760
#define SM_GP  45760                         // 160*34 = 5440 -> 51200
#define SM_LF  51200                         // 128 -> 51328
#define SM_HS  51328                         // 288 -> 51616
#define SM_CS  51616                         // 288 -> 51904
#define SM_MB  51904                         // 8B aligned (51904*4 % 8 == 0)
#define SM_TOT ((51906) * 4)

__global__ __launch_bounds__(512, 1) __cluster_dims__(4, 1, 1)
void k_main(const int* __restrict__ labels,
            const float* __restrict__ W,
            const float* __restrict__ leaf,
            float* __restrict__ out) {
    const int bx = blockIdx.x;
    if ((bx >> 2) >= 32) return;   // dummy clusters

    extern __shared__ float sm[];
    float* W_T    = sm + SM_WT;    // [160 rr=jj*5+g][260]
    float* Xbuf   = sm + SM_X;     // 2 x [8][260]
    float* Gp     = sm + SM_GP;    // [160][34] f32 partials
    float* leaf_s = sm + SM_LF;
    float* hstage = sm + SM_HS;    // [8][36]
    float* cstage = sm + SM_CS;

    const int r   = bx & 3;
    const int B   = (bx >> 2) * 8;
    const int tid = threadIdx.x;
    const int r32 = r * 32;
    const uint32_t mb = (uint32_t)__cvta_generic_to_shared(sm + SM_MB);
    const uint32_t xbase = (uint32_t)__cvta_generic_to_shared(Xbuf);

    // nonlin / schedule roles (tid < 256 only)
    const int b   = tid & 7;
    const int jj  = (tid & 255) >> 3;
    // cp.async roles (tid < 256)
    const int b2  = (tid & 255) >> 5;
    const int s2  = tid & 31;
    // GEMM roles (all 512)
    const int ks  = tid >> 7;      // k-quarter 0..3 (0,1: left; 2,3: right)
    const int w128 = tid & 127;
    const int bgq = w128 & 3;      // batch pair index (batches bgq*2, bgq*2+1)
    const int jg  = w128 >> 2;     // hdim 0..31
    // push roles (tid < 256)
    const int ptgt = (tid & 255) >> 6;
    const int pb   = (tid & 63) >> 3;
    const int pc   = tid & 7;
    // writeback roles (all 512: lower half h, upper half c)
    const int b3  = (tid & 255) >> 5;
    const int s3  = tid & 31;

    // ---- prologue: W_T[rr=jj*5+g][k] = W[64+k][g*H + r32 + jj] ----
    {
        int rr = tid & 255;
        if (rr < 160 && tid < 256) {
            int wjj = rr / 5, wg = rr % 5;
            for (int k = 0; k < 256; k++)
                W_T[rr * WROW + k] = __ldg(&W[(64 + k) * G5 + wg * H + r32 + wjj]);
        }
    }
    if (tid < 128) leaf_s[tid] = leaf[tid];
    if (tid == 0)
        asm volatile("mbarrier.init.shared.b64 [%0], %1;" :: "r"(mb), "r"(4) : "memory");
    __syncthreads();
    asm volatile("barrier.cluster.arrive.aligned;" ::: "memory");
    asm volatile("barrier.cluster.wait.aligned;" ::: "memory");

    // leafW for nonlin roles (b, jj), tid<256
    float lw5[5];
#pragma unroll
    for (int g = 0; g < 5; g++) lw5[g] = 0.0f;
    if (tid < 256) {
        for (int k = 0; k < 128; k++) {
            float lv = leaf_s[k];
#pragma unroll
            for (int g = 0; g < 5; g++)
                lw5[g] += lv * (W_T[(jj * 5 + g) * WROW + k]
                              + W_T[(jj * 5 + g) * WROW + 128 + k]);
        }
    }

    // schedule regs (tid<256)
    int liA = -1, liB = -1, labB = 0;
    float tab5[5] = {0, 0, 0, 0, 0};
    float cl = 0.0f;
    if (tid < 256) {
        liA  = __ldg(&g_lidx[B + b]);
        liB  = __ldg(&g_lidx[NBAT + B + b]);
        labB = __ldg(&labels[NBAT + B + b]);
        int labA = __ldg(&labels[B + b]);
#pragma unroll
        for (int g = 0; g < 5; g++)
            tab5[g] = __ldg(&g_table[(size_t)labA * G5 + g * H + r32 + jj]);
        cl = leaf_s[r32 + jj];
    }
    float cprev = 0.0f;
    int cur = 0;

    for (int t = 0; t < D; t++) {
        float* Xc = Xbuf + cur * XBUF;
        const int nxt = cur ^ 1;

        float cln = 0.0f, t5n[5] = {0, 0, 0, 0, 0};
        int liC = 0, labC = 0;
        int li2 = -1;
        if (t < D - 1 && tid < 256) {
            bool redB = (liB >= 0);
            cln = redB
                ? ((liB == t - 1) ? cprev
                   : __ldcg(&g_cst[(size_t)liB * NH + (B + b) * H + r32 + jj]))
                : leaf_s[r32 + jj];
#pragma unroll
            for (int g = 0; g < 5; g++)
                t5n[g] = __ldg(&g_table[(size_t)labB * G5 + g * H + r32 + jj]);
            const int t2 = (t + 2 < D) ? (t + 2) : (D - 1);
            liC  = __ldg(&g_lidx[t2 * NBAT + B + b]);
            labC = __ldg(&labels[t2 * NBAT + B + b]);

            // cp.async for X[next] left (global path only)
            li2 = __ldg(&g_lidx[(t + 1) * NBAT + B + b2]);
            if (li2 >= 0 && li2 != t - 1) {
                uint32_t dst = xbase + (nxt * XBUF + b2 * XK + s2 * 4) * 4;
                const float* src = &g_hst[(size_t)li2 * NH + (B + b2) * H + s2 * 4];
                asm volatile("cp.async.cg.shared.global [%0], [%1], 16;"
                             :: "r"(dst), "l"(src) : "memory");
            }
            asm volatile("cp.async.commit_group;" ::: "memory");
        }

        // ---- GEMM accumulators (2 batches x 5 gates) ----
        unsigned long long acc[2][5];
#pragma unroll
        for (int i = 0; i < 2; i++)
#pragma unroll
            for (int g = 0; g < 5; g++) acc[i][g] = 0ULL;

        const float* xb0 = Xc + (bgq * 2) * XK + ks * 64;
        const ulonglong2* wp =
            reinterpret_cast<const ulonglong2*>(W_T + (jg * 5) * WROW + ks * 64);

        // ---- LEFT half (ks<2, k<128): valid at loop top ----
        if (ks < 2) {
#pragma unroll 4
            for (int p = 0; p < 16; p++) {
                ulonglong2 xv[2];
#pragma unroll
                for (int i = 0; i < 2; i++)
                    xv[i] = *reinterpret_cast<const ulonglong2*>(xb0 + i * XK + p * 4);
#pragma unroll
                for (int g = 0; g < 5; g++) {
                    ulonglong2 wv = wp[g * 65 + p];
#pragma unroll
                    for (int i = 0; i < 2; i++) {
                        asm("fma.rn.f32x2 %0, %1, %2, %0;"
                            : "+l"(acc[i][g]) : "l"(xv[i].x), "l"(wv.x));
                        asm("fma.rn.f32x2 %0, %1, %2, %0;"
                            : "+l"(acc[i][g]) : "l"(xv[i].y), "l"(wv.y));
                    }
                }
            }
        }

        // ---- deferred handshake wait: protects X[cur] right ----
        if (t > 0) {
            const unsigned par = (t - 1) & 1;
            asm volatile(
                "{\n\t"
                ".reg .pred P;\n\t"
                "WL%=:\n\t"
                "mbarrier.try_wait.parity.acquire.cluster.shared::cta.b64 P, [%0], %1, 0x989680;\n\t"
                "@P bra WD%=;\n\t"
                "bra WL%=;\n\t"
                "WD%=:\n\t"
                "}" :: "r"(mb), "r"(par) : "memory");
        }

        // local copy: X[next] left <- X[cur] right (left child == t-1)
        if (tid < 256 && li2 == t - 1 && li2 >= 0) {
            float4 v = *reinterpret_cast<const float4*>(&Xc[b2 * XK + 128 + s2 * 4]);
            *reinterpret_cast<float4*>(&Xbuf[nxt * XBUF + b2 * XK + s2 * 4]) = v;
        }

        // ---- RIGHT half (ks>=2, k>=128): needs pushes of h(t-1) ----
        if (ks >= 2) {
#pragma unroll 4
            for (int p = 0; p < 16; p++) {
                ulonglong2 xv[2];
#pragma unroll
                for (int i = 0; i < 2; i++)
                    xv[i] = *reinterpret_cast<const ulonglong2*>(xb0 + i * XK + p * 4);
#pragma unroll
                for (int g = 0; g < 5; g++) {
                    ulonglong2 wv = wp[g * 65 + p];
#pragma unroll
                    for (int i = 0; i < 2; i++) {
                        asm("fma.rn.f32x2 %0, %1, %2, %0;"
                            : "+l"(acc[i][g]) : "l"(xv[i].x), "l"(wv.x));
                        asm("fma.rn.f32x2 %0, %1, %2, %0;"
                            : "+l"(acc[i][g]) : "l"(xv[i].y), "l"(wv.y));
                    }
                }
            }
        }

        // partials -> Gp (f32, summed pair)
#pragma unroll
        for (int g = 0; g < 5; g++)
#pragma unroll
            for (int i = 0; i < 2; i++)
                Gp[(jg * 5 + g) * GPR + ks * 8 + bgq * 2 + i] =
                    ull_lo(acc[i][g]) + ull_hi(acc[i][g]);
        __syncthreads();   // (1)

        // ---- reduce + nonlinearity: tid<256, thread owns (b, jj) ----
        if (tid < 256) {
            float gate[5];
            if (liA >= 0) {
#pragma unroll
                for (int g = 0; g < 5; g++) {
                    float s = tab5[g];
#pragma unroll
                    for (int q2 = 0; q2 < 4; q2++)
                        s += Gp[(jj * 5 + g) * GPR + q2 * 8 + b];
                    gate[g] = s;
                }
            } else {
#pragma unroll
                for (int g = 0; g < 5; g++) gate[g] = tab5[g] + lw5[g];
            }
            float lf  = leaf_s[r32 + jj];
            float clv = (liA >= 0) ? cl    : lf;
            float crv = (liA >= 0) ? cprev : lf;
            float c = sigf(gate[0]) * tanhfast(gate[4])
                    + sigf(gate[1]) * clv + sigf(gate[2]) * crv;
            float h = sigf(gate[3]) * tanhfast(c);
            cprev = c;
            hstage[b * HSROW + jj] = h;
            cstage[b * HSROW + jj] = c;
        }
        __syncthreads();   // (2)

        // ---- coalesced v4 push into X[next] right (tid<256) ----
        if (t < D - 1 && tid < 256) {
            float4 v = *reinterpret_cast<const float4*>(&hstage[pb * HSROW + pc * 4]);
            uint32_t xaddr = xbase + (nxt * XBUF + pb * XK + 128 + r32 + pc * 4) * 4;
            if (ptgt == r) {
                *reinterpret_cast<float4*>(
                    &Xbuf[nxt * XBUF + pb * XK + 128 + r32 + pc * 4]) = v;
            } else {
                uint32_t rem;
                asm("mapa.shared::cluster.u32 %0, %1, %2;"
                    : "=r"(rem) : "r"(xaddr), "r"(ptgt));
                asm volatile("st.shared::cluster.v4.f32 [%0], {%1, %2, %3, %4};"
                             :: "r"(rem), "f"(v.x), "f"(v.y), "f"(v.z), "f"(v.w)
                             : "memory");
            }
        }
        // ---- writeback: lower half h, upper half c ----
        {
            const size_t o = (size_t)t * NH + (B + b3) * H + r32 + s3;
            if (tid < 256) {
                float hv = hstage[b3 * HSROW + s3];
                __stcg(&g_hst[o], hv);
                if (t == D - 1) out[NH + (B + b3) * H + r32 + s3] = hv;  // embeddings
            } else {
                float cv = cstage[b3 * HSROW + s3];
                __stcg(&g_cst[o], cv);
                if (t == D - 1) out[(B + b3) * H + r32 + s3] = cv;       // cells
            }
        }
        // cp.async completion BEFORE the barrier that releases readers
        if (t < D - 1 && tid < 256)
            asm volatile("cp.async.wait_group 0;" ::: "memory");
        __syncthreads();   // (3)

        // ---- release arrive (wait deferred into next step) ----
        if (t < D - 1) {
            if (tid < 4) {
                uint32_t rem;
                asm("mapa.shared::cluster.u32 %0, %1, %2;"
                    : "=r"(rem) : "r"(mb), "r"(tid));
                asm volatile("mbarrier.arrive.release.cluster.shared::cluster.b64 _, [%0];"
                             :: "r"(rem) : "memory");
            }
        }

        liA = liB; liB = liC; labB = labC;
        cl = cln;
#pragma unroll
        for (int g = 0; g < 5; g++) tab5[g] = t5n[g];
        cur ^= 1;
    }

    asm volatile("barrier.cluster.arrive.aligned;" ::: "memory");
    asm volatile("barrier.cluster.wait.aligned;" ::: "memory");
}

// ============================================================
extern "C" void kernel_launch(void* const* d_in, const int* in_sizes, int n_in,
                              void* d_out, int out_size) {
    const int*   trans  = (const int*)d_in[0];
    const int*   labels = (const int*)d_in[1];
    const float* emb    = (const float*)d_in[2];
    const float* W      = (const float*)d_in[3];
    const float* bias   = (const float*)d_in[4];
    const float* leaf   = (const float*)d_in[5];
    float* out = (float*)d_out;

    cudaFuncSetAttribute(k_pre, cudaFuncAttributeMaxDynamicSharedMemorySize,
                         64 * 33 * 4 + 64 * 160 * 4);
    cudaFuncSetAttribute(k_main, cudaFuncAttributeMaxDynamicSharedMemorySize,
                         SM_TOT);

    dim3 pgrid(NV / 32, 5);
    k_pre<<<pgrid, 256, 64 * 33 * 4 + 64 * 160 * 4>>>(emb, W, bias, trans);
    k_main<<<148, 512, SM_TOT>>>(labels, W, leaf, out);
}

// round 13
// speedup vs baseline: 1.1046x; 1.1046x over previous
#include <cuda_runtime.h>
#include <cstdint>

#define D    512
#define NBAT 256
#define H    128
#define LDIM 64
#define NV   32000
#define G5   640          // 5*H
#define NH   (NBAT*H)     // 32768

// ---- persistent device scratch (allocation-free rule) ----
__device__ float g_hst[D * NBAT * H];     // 64 MB
__device__ float g_cst[D * NBAT * H];     // 64 MB
__device__ float g_table[(size_t)NV * G5];// 82 MB: emb@W[0:64] + b
__device__ int   g_lidx[D * NBAT];        // left-child step index, -1 = shift

__device__ __forceinline__ float sigf(float x) {
    return __fdividef(1.0f, 1.0f + __expf(-x));
}
__device__ __forceinline__ float tanhfast(float x) {
    return 1.0f - __fdividef(2.0f, __expf(2.0f * x) + 1.0f);
}
__device__ __forceinline__ float ull_lo(unsigned long long v) {
    return __uint_as_float((unsigned)(v & 0xffffffffull));
}
__device__ __forceinline__ float ull_hi(unsigned long long v) {
    return __uint_as_float((unsigned)(v >> 32));
}

// ============================================================
// K_pre: grid (1000, 5). y<4: table tiles; y==4,x==0: lidx sim.
// ============================================================
__global__ __launch_bounds__(256) void k_pre(const float* __restrict__ emb,
                                             const float* __restrict__ W,
                                             const float* __restrict__ bias,
                                             const int* __restrict__ trans) {
    if (blockIdx.y == 4) {
        if (blockIdx.x != 0) return;
        int b = threadIdx.x;
        short st[D];
        int ptr = 0;
        for (int t = 0; t < D; t++) {
            int m = trans[t * NBAT + b];
            int lx = -1;
            if (m) lx = st[ptr - 2];
            int np = ptr - 2 * m;
            st[np] = (short)t;
            ptr = np + 1;
            g_lidx[t * NBAT + b] = lx;
        }
        return;
    }
    extern __shared__ float sm[];
    float* emb_s = sm;              // [64][33]
    float* W_sc  = sm + 64 * 33;    // [64][160]
    const int v0 = blockIdx.x * 32;
    const int c0 = blockIdx.y * 160;
    const int tid = threadIdx.x;

    for (int idx = tid; idx < 32 * 64; idx += 256) {
        int vv = idx >> 6, k = idx & 63;
        emb_s[k * 33 + vv] = emb[(v0 + vv) * LDIM + k];
    }
    for (int idx = tid; idx < 64 * 40; idx += 256) {
        int k = idx / 40, cq = idx % 40;
        float4 w4 = *reinterpret_cast<const float4*>(&W[k * G5 + c0 + cq * 4]);
        *reinterpret_cast<float4*>(&W_sc[k * 160 + cq * 4]) = w4;
    }
    __syncthreads();

    const int vg = tid & 7;
    const int cg = tid >> 3;
    float acc[4][5];
#pragma unroll
    for (int j = 0; j < 5; j++) {
        float bj = __ldg(&bias[c0 + cg * 5 + j]);
#pragma unroll
        for (int i = 0; i < 4; i++) acc[i][j] = bj;
    }
#pragma unroll 4
    for (int k = 0; k < 64; k++) {
        float x[4], w[5];
#pragma unroll
        for (int i = 0; i < 4; i++) x[i] = emb_s[k * 33 + vg * 4 + i];
#pragma unroll
        for (int j = 0; j < 5; j++) w[j] = W_sc[k * 160 + cg * 5 + j];
#pragma unroll
        for (int i = 0; i < 4; i++)
#pragma unroll
            for (int j = 0; j < 5; j++) acc[i][j] += x[i] * w[j];
    }
#pragma unroll
    for (int i = 0; i < 4; i++)
#pragma unroll
        for (int j = 0; j < 5; j++)
            g_table[(size_t)(v0 + vg * 4 + i) * G5 + c0 + cg * 5 + j] = acc[i][j];
}

// ============================================================
// Main: 32 active clusters of 4 CTAs (grid 148), 256 thr/CTA.
// R13 = R11 + : scalar self-push in nonlin (drops one sync),
// writeback deferred after arrive, wait_group before pre-arrive sync.
// ============================================================
#define XK     260
#define WROW   260
#define XBUF   (8 * XK)                      // 2080 floats
#define HSROW  36
#define GPR    66
#define SM_WT  0                             // 160*260 = 41600
#define SM_X   41600                         // + 4160 -> 45760
#define SM_GP  45760                         // 160*66 = 10560 -> 56320
#define SM_LF  56320                         // 128 -> 56448
#define SM_HS  56448                         // 288 -> 56736
#define SM_CS  56736                         // 288 -> 57024
#define SM_MB  57024                         // 8B aligned
#define SM_TOT ((57026) * 4)

__global__ __launch_bounds__(256, 1) __cluster_dims__(4, 1, 1)
void k_main(const int* __restrict__ labels,
            const float* __restrict__ W,
            const float* __restrict__ leaf,
            float* __restrict__ out) {
    const int bx = blockIdx.x;
    if ((bx >> 2) >= 32) return;   // dummy clusters

    extern __shared__ float sm[];
    float* W_T    = sm + SM_WT;    // [160 rr=jj*5+g][260]
    float* Xbuf   = sm + SM_X;     // 2 x [8][260]
    float* Gp     = sm + SM_GP;    // [160][66]
    float* leaf_s = sm + SM_LF;
    float* hstage = sm + SM_HS;    // [8][36]
    float* cstage = sm + SM_CS;

    const int r   = bx & 3;
    const int B   = (bx >> 2) * 8;
    const int tid = threadIdx.x;
    const int r32 = r * 32;
    const uint32_t mb = (uint32_t)__cvta_generic_to_shared(sm + SM_MB);
    const uint32_t xbase = (uint32_t)__cvta_generic_to_shared(Xbuf);

    // roles
    const int b   = tid & 7;       // nonlin batch
    const int jj  = tid >> 3;      // nonlin hdim
    const int b2  = tid >> 5;      // cp.async / writeback batch
    const int s2  = tid & 31;
    // GEMM roles
    const int ks  = tid >> 6;      // k-quarter 0..3 (0,1: left; 2,3: right)
    const int w64 = tid & 63;
    const int bgq = w64 & 1;
    const int jg  = w64 >> 1;

    // ---- prologue: W_T[rr=jj*5+g][k] = W[64+k][g*H + r32 + jj] ----
    {
        int rr = tid < 160 ? tid : 0;
        int wjj = rr / 5, wg = rr % 5;
        for (int k = 0; k < 256; k++) {
            if (tid < 160)
                W_T[rr * WROW + k] = __ldg(&W[(64 + k) * G5 + wg * H + r32 + wjj]);
        }
    }
    if (tid < 128) leaf_s[tid] = leaf[tid];
    if (tid == 0)
        asm volatile("mbarrier.init.shared.b64 [%0], %1;" :: "r"(mb), "r"(4) : "memory");
    __syncthreads();
    asm volatile("barrier.cluster.arrive.aligned;" ::: "memory");
    asm volatile("barrier.cluster.wait.aligned;" ::: "memory");

    // leafW for nonlin roles (b, jj)
    float lw5[5];
#pragma unroll
    for (int g = 0; g < 5; g++) lw5[g] = 0.0f;
    for (int k = 0; k < 128; k++) {
        float lv = leaf_s[k];
#pragma unroll
        for (int g = 0; g < 5; g++)
            lw5[g] += lv * (W_T[(jj * 5 + g) * WROW + k]
                          + W_T[(jj * 5 + g) * WROW + 128 + k]);
    }

    // schedule regs
    int liA  = __ldg(&g_lidx[B + b]);
    int liB  = __ldg(&g_lidx[NBAT + B + b]);
    int labB = __ldg(&labels[NBAT + B + b]);
    float tab5[5];
    {
        int labA = __ldg(&labels[B + b]);
#pragma unroll
        for (int g = 0; g < 5; g++)
            tab5[g] = __ldg(&g_table[(size_t)labA * G5 + g * H + r32 + jj]);
    }
    float cl = leaf_s[r32 + jj];
    float cprev = 0.0f;
    int cur = 0;

    for (int t = 0; t < D; t++) {
        float* Xc = Xbuf + cur * XBUF;
        const int nxt = cur ^ 1;

        float cln = 0.0f, t5n[5];
        int liC = 0, labC = 0;
        int li2 = -1;
        if (t < D - 1) {
            bool redB = (liB >= 0);
            cln = redB
                ? ((liB == t - 1) ? cprev
                   : __ldcg(&g_cst[(size_t)liB * NH + (B + b) * H + r32 + jj]))
                : leaf_s[r32 + jj];
#pragma unroll
            for (int g = 0; g < 5; g++)
                t5n[g] = __ldg(&g_table[(size_t)labB * G5 + g * H + r32 + jj]);
            const int t2 = (t + 2 < D) ? (t + 2) : (D - 1);
            liC  = __ldg(&g_lidx[t2 * NBAT + B + b]);
            labC = __ldg(&labels[t2 * NBAT + B + b]);

            // cp.async for X[next] left (global path only; li2==t-1 deferred)
            li2 = __ldg(&g_lidx[(t + 1) * NBAT + B + b2]);
            if (li2 >= 0 && li2 != t - 1) {
                uint32_t dst = xbase + (nxt * XBUF + b2 * XK + s2 * 4) * 4;
                const float* src = &g_hst[(size_t)li2 * NH + (B + b2) * H + s2 * 4];
                asm volatile("cp.async.cg.shared.global [%0], [%1], 16;"
                             :: "r"(dst), "l"(src) : "memory");
            }
            asm volatile("cp.async.commit_group;" ::: "memory");
        }

        // ---- GEMM accumulators ----
        unsigned long long acc[4][5];
#pragma unroll
        for (int i = 0; i < 4; i++)
#pragma unroll
            for (int g = 0; g < 5; g++) acc[i][g] = 0ULL;

        const float* xb0 = Xc + (bgq * 4) * XK + ks * 64;
        const ulonglong2* wp =
            reinterpret_cast<const ulonglong2*>(W_T + (jg * 5) * WROW + ks * 64);

        // ---- LEFT half first for ks<2 (k<128): valid at loop top ----
        if (ks < 2) {
#pragma unroll 4
            for (int p = 0; p < 16; p++) {
                ulonglong2 xv[4];
#pragma unroll
                for (int i = 0; i < 4; i++)
                    xv[i] = *reinterpret_cast<const ulonglong2*>(xb0 + i * XK + p * 4);
#pragma unroll
                for (int g = 0; g < 5; g++) {
                    ulonglong2 wv = wp[g * 65 + p];
#pragma unroll
                    for (int i = 0; i < 4; i++) {
                        asm("fma.rn.f32x2 %0, %1, %2, %0;"
                            : "+l"(acc[i][g]) : "l"(xv[i].x), "l"(wv.x));
                        asm("fma.rn.f32x2 %0, %1, %2, %0;"
                            : "+l"(acc[i][g]) : "l"(xv[i].y), "l"(wv.y));
                    }
                }
            }
        }

        // ---- deferred handshake wait (h_{t-1}): protects X[cur] right ----
        if (t > 0) {
            const unsigned par = (t - 1) & 1;
            asm volatile(
                "{\n\t"
                ".reg .pred P;\n\t"
                "WL%=:\n\t"
                "mbarrier.try_wait.parity.acquire.cluster.shared::cta.b64 P, [%0], %1, 0x989680;\n\t"
                "@P bra WD%=;\n\t"
                "bra WL%=;\n\t"
                "WD%=:\n\t"
                "}" :: "r"(mb), "r"(par) : "memory");
        }

        // local copy: X[next] left <- X[cur] right (left child == t-1)
        if (li2 == t - 1 && li2 >= 0) {
            float4 v = *reinterpret_cast<const float4*>(&Xc[b2 * XK + 128 + s2 * 4]);
            *reinterpret_cast<float4*>(&Xbuf[nxt * XBUF + b2 * XK + s2 * 4]) = v;
        }

        // ---- RIGHT half for ks>=2 (k>=128): needs pushes of h(t-1) ----
        if (ks >= 2) {
#pragma unroll 4
            for (int p = 0; p < 16; p++) {
                ulonglong2 xv[4];
#pragma unroll
                for (int i = 0; i < 4; i++)
                    xv[i] = *reinterpret_cast<const ulonglong2*>(xb0 + i * XK + p * 4);
#pragma unroll
                for (int g = 0; g < 5; g++) {
                    ulonglong2 wv = wp[g * 65 + p];
#pragma unroll
                    for (int i = 0; i < 4; i++) {
                        asm("fma.rn.f32x2 %0, %1, %2, %0;"
                            : "+l"(acc[i][g]) : "l"(xv[i].x), "l"(wv.x));
                        asm("fma.rn.f32x2 %0, %1, %2, %0;"
                            : "+l"(acc[i][g]) : "l"(xv[i].y), "l"(wv.y));
                    }
                }
            }
        }

        // partials -> Gp
#pragma unroll
        for (int g = 0; g < 5; g++)
#pragma unroll
            for (int i = 0; i < 4; i++)
                *reinterpret_cast<unsigned long long*>(
                    &Gp[(jg * 5 + g) * GPR + ks * 16 + (bgq * 4 + i) * 2]) = acc[i][g];
        __syncthreads();   // (1)

        // ---- reduce + nonlinearity + SELF-PUSH: thread owns (b, jj) ----
        {
            float gate[5];
            if (liA >= 0) {
#pragma unroll
                for (int g = 0; g < 5; g++) {
                    float s = tab5[g];
#pragma unroll
                    for (int q2 = 0; q2 < 4; q2++) {
                        unsigned long long pv = *reinterpret_cast<unsigned long long*>(
                            &Gp[(jj * 5 + g) * GPR + q2 * 16 + b * 2]);
                        s += ull_lo(pv) + ull_hi(pv);
                    }
                    gate[g] = s;
                }
            } else {
#pragma unroll
                for (int g = 0; g < 5; g++) gate[g] = tab5[g] + lw5[g];
            }
            float lf  = leaf_s[r32 + jj];
            float clv = (liA >= 0) ? cl    : lf;
            float crv = (liA >= 0) ? cprev : lf;
            float c = sigf(gate[0]) * tanhfast(gate[4])
                    + sigf(gate[1]) * clv + sigf(gate[2]) * crv;
            float h = sigf(gate[3]) * tanhfast(c);
            cprev = c;
            hstage[b * HSROW + jj] = h;
            cstage[b * HSROW + jj] = c;
            // push own h into all 4 CTAs' X[next] right half
            if (t < D - 1) {
                uint32_t xaddr = xbase + (nxt * XBUF + b * XK + 128 + r32 + jj) * 4;
#pragma unroll
                for (int cta = 0; cta < 4; cta++) {
                    uint32_t rem;
                    asm("mapa.shared::cluster.u32 %0, %1, %2;"
                        : "=r"(rem) : "r"(xaddr), "r"(cta));
                    asm volatile("st.shared::cluster.f32 [%0], %1;"
                                 :: "r"(rem), "f"(h) : "memory");
                }
            }
        }

        // cp.async completion BEFORE the barrier that releases readers
        if (t < D - 1)
            asm volatile("cp.async.wait_group 0;" ::: "memory");
        __syncthreads();   // (2): pushes + stage + cp.async complete

        // ---- release arrive ASAP (wait deferred into next step) ----
        if (t < D - 1 && tid < 4) {
            uint32_t rem;
            asm("mapa.shared::cluster.u32 %0, %1, %2;"
                : "=r"(rem) : "r"(mb), "r"(tid));
            asm volatile("mbarrier.arrive.release.cluster.shared::cluster.b64 _, [%0];"
                         :: "r"(rem) : "memory");
        }

        // ---- writeback AFTER arrive (off the cluster critical path) ----
        {
            float hv = hstage[b2 * HSROW + s2];
            float cv = cstage[b2 * HSROW + s2];
            const size_t o = (size_t)t * NH + (B + b2) * H + r32 + s2;
            __stcg(&g_hst[o], hv);
            __stcg(&g_cst[o], cv);
            if (t == D - 1) {
                out[(B + b2) * H + r32 + s2]      = cv;   // cells
                out[NH + (B + b2) * H + r32 + s2] = hv;   // embeddings
            }
        }

        liA = liB; liB = liC; labB = labC;
        cl = cln;
#pragma unroll
        for (int g = 0; g < 5; g++) tab5[g] = t5n[g];
        cur ^= 1;
    }

    asm volatile("barrier.cluster.arrive.aligned;" ::: "memory");
    asm volatile("barrier.cluster.wait.aligned;" ::: "memory");
}

// ============================================================
extern "C" void kernel_launch(void* const* d_in, const int* in_sizes, int n_in,
                              void* d_out, int out_size) {
    const int*   trans  = (const int*)d_in[0];
    const int*   labels = (const int*)d_in[1];
    const float* emb    = (const float*)d_in[2];
    const float* W      = (const float*)d_in[3];
    const float* bias   = (const float*)d_in[4];
    const float* leaf   = (const float*)d_in[5];
    float* out = (float*)d_out;

    cudaFuncSetAttribute(k_pre, cudaFuncAttributeMaxDynamicSharedMemorySize,
                         64 * 33 * 4 + 64 * 160 * 4);
    cudaFuncSetAttribute(k_main, cudaFuncAttributeMaxDynamicSharedMemorySize,
                         SM_TOT);

    dim3 pgrid(NV / 32, 5);
    k_pre<<<pgrid, 256, 64 * 33 * 4 + 64 * 160 * 4>>>(emb, W, bias, trans);
    k_main<<<148, 256, SM_TOT>>>(labels, W, leaf, out);
}

// round 15
// speedup vs baseline: 1.1564x; 1.0468x over previous
#include <cuda_runtime.h>
#include <cstdint>

#define D    512
#define NBAT 256
#define H    128
#define LDIM 64
#define NV   32000
#define G5   640          // 5*H
#define NH   (NBAT*H)     // 32768

// ---- persistent device scratch (allocation-free rule) ----
__device__ float g_hst[D * NBAT * H];     // 64 MB
__device__ float g_cst[D * NBAT * H];     // 64 MB
__device__ float g_table[(size_t)NV * G5];// 82 MB: emb@W[0:64] + b
__device__ int   g_lidx[D * NBAT];        // left-child step index, -1 = shift
__device__ int   g_cslot[D * NBAT];       // compacted slot (-1 = shift)
__device__ int   g_cnt[D * 32];           // reduce count per (t, cluster-of-8)

__device__ __forceinline__ float sigf(float x) {
    return __fdividef(1.0f, 1.0f + __expf(-x));
}
__device__ __forceinline__ float tanhfast(float x) {
    return 1.0f - __fdividef(2.0f, __expf(2.0f * x) + 1.0f);
}
__device__ __forceinline__ float ull_lo(unsigned long long v) {
    return __uint_as_float((unsigned)(v & 0xffffffffull));
}
__device__ __forceinline__ float ull_hi(unsigned long long v) {
    return __uint_as_float((unsigned)(v >> 32));
}

// ============================================================
// K_pre: grid (1000, 5). y<4: table tiles; y==4,x==0: stack sim
// + compaction map (ballot over 8-batch clusters).
// ============================================================
__global__ __launch_bounds__(256) void k_pre(const float* __restrict__ emb,
                                             const float* __restrict__ W,
                                             const float* __restrict__ bias,
                                             const int* __restrict__ trans) {
    if (blockIdx.y == 4) {
        if (blockIdx.x != 0) return;
        int b = threadIdx.x;
        short st[D];
        int ptr = 0;
        for (int t = 0; t < D; t++) {
            int m = trans[t * NBAT + b];
            int lx = -1;
            if (m) lx = st[ptr - 2];
            int np = ptr - 2 * m;
            st[np] = (short)t;
            ptr = np + 1;
            g_lidx[t * NBAT + b] = lx;
            unsigned bal = __ballot_sync(0xffffffffu, lx >= 0);
            int grp = (b >> 3) & 3;
            unsigned byte = (bal >> (grp * 8)) & 0xffu;
            int slot = __popc(byte & ((1u << (b & 7)) - 1u));
            g_cslot[t * NBAT + b] = (lx >= 0) ? slot : -1;
            if ((b & 7) == 0) g_cnt[t * 32 + (b >> 3)] = __popc(byte);
        }
        return;
    }
    extern __shared__ float sm[];
    float* emb_s = sm;              // [64][33]
    float* W_sc  = sm + 64 * 33;    // [64][160]
    const int v0 = blockIdx.x * 32;
    const int c0 = blockIdx.y * 160;
    const int tid = threadIdx.x;

    for (int idx = tid; idx < 32 * 64; idx += 256) {
        int vv = idx >> 6, k = idx & 63;
        emb_s[k * 33 + vv] = emb[(v0 + vv) * LDIM + k];
    }
    for (int idx = tid; idx < 64 * 40; idx += 256) {
        int k = idx / 40, cq = idx % 40;
        float4 w4 = *reinterpret_cast<const float4*>(&W[k * G5 + c0 + cq * 4]);
        *reinterpret_cast<float4*>(&W_sc[k * 160 + cq * 4]) = w4;
    }
    __syncthreads();

    const int vg = tid & 7;
    const int cg = tid >> 3;
    float acc[4][5];
#pragma unroll
    for (int j = 0; j < 5; j++) {
        float bj = __ldg(&bias[c0 + cg * 5 + j]);
#pragma unroll
        for (int i = 0; i < 4; i++) acc[i][j] = bj;
    }
#pragma unroll 4
    for (int k = 0; k < 64; k++) {
        float x[4], w[5];
#pragma unroll
        for (int i = 0; i < 4; i++) x[i] = emb_s[k * 33 + vg * 4 + i];
#pragma unroll
        for (int j = 0; j < 5; j++) w[j] = W_sc[k * 160 + cg * 5 + j];
#pragma unroll
        for (int i = 0; i < 4; i++)
#pragma unroll
            for (int j = 0; j < 5; j++) acc[i][j] += x[i] * w[j];
    }
#pragma unroll
    for (int i = 0; i < 4; i++)
#pragma unroll
        for (int j = 0; j < 5; j++)
            g_table[(size_t)(v0 + vg * 4 + i) * G5 + c0 + cg * 5 + j] = acc[i][j];
}

// ============================================================
// Main: 32 active clusters of 4 CTAs (grid 148), 256 thr/CTA.
// R15 = R14 + bmap clamp (dead slots read batch 0, results discarded).
// ============================================================
#define XR     132
#define XBUF   (8 * XR)                      // 1056 floats
#define WROW   260
#define HSROW  36
#define GPR    66
#define SM_WT  0                             // 160*260 = 41600
#define SM_X   41600                         // Xs 2*1056 -> 43712
#define SM_HP  43712                         // hprev 2*1056 -> 45824
#define SM_GP  45824                         // 160*66 = 10560 -> 56384
#define SM_LF  56384                         // 128 -> 56512
#define SM_HS  56512                         // 288 -> 56800
#define SM_CS  56800                         // 288 -> 57088
#define SM_BM  57088                         // bmap 2*8 ints -> 57104
#define SM_MB  57104                         // 8B aligned
#define SM_TOT ((57106) * 4)

__global__ __launch_bounds__(256, 1) __cluster_dims__(4, 1, 1)
void k_main(const int* __restrict__ labels,
            const float* __restrict__ W,
            const float* __restrict__ leaf,
            float* __restrict__ out) {
    const int bx = blockIdx.x;
    if ((bx >> 2) >= 32) return;   // dummy clusters

    extern __shared__ float sm[];
    float* W_T    = sm + SM_WT;    // [160 rr=jj*5+g][260]
    float* Xs     = sm + SM_X;     // 2 x [8 slots][132] left halves
    float* hprev  = sm + SM_HP;    // 2 x [8 batch][132] h(t-1)
    float* Gp     = sm + SM_GP;    // [160][66]
    float* leaf_s = sm + SM_LF;
    float* hstage = sm + SM_HS;    // [8][36]
    float* cstage = sm + SM_CS;
    int*   bmap_s = (int*)(sm + SM_BM);  // [2][8] slot -> batch

    const int r   = bx & 3;
    const int cl  = bx >> 2;       // cluster id
    const int B   = cl * 8;
    const int tid = threadIdx.x;
    const int r32 = r * 32;
    const uint32_t mb = (uint32_t)__cvta_generic_to_shared(sm + SM_MB);
    const uint32_t hpb = (uint32_t)__cvta_generic_to_shared(hprev);

    // roles
    const int b   = tid & 7;       // nonlin batch
    const int jj  = tid >> 3;      // nonlin hdim
    const int b2  = tid >> 5;      // cp.async / writeback batch
    const int s2  = tid & 31;
    // GEMM roles (warp-uniform bgq & ks; each SMSP: 1 left + 1 right, bg0 + bg1)
    const int wid = tid >> 5;
    const int bgq = wid >> 2;                          // 0 or 1
    const int ks  = (wid + ((wid >> 2) << 1)) & 3;     // 0..3; <2 = left
    const int jg  = tid & 31;

    // ---- prologue: W_T[rr=jj*5+g][k] = W[64+k][g*H + r32 + jj] ----
    {
        int rr = tid < 160 ? tid : 0;
        int wjj = rr / 5, wg = rr % 5;
        for (int k = 0; k < 256; k++) {
            if (tid < 160)
                W_T[rr * WROW + k] = __ldg(&W[(64 + k) * G5 + wg * H + r32 + wjj]);
        }
    }
    if (tid < 128) leaf_s[tid] = leaf[tid];
    if (tid == 0)
        asm volatile("mbarrier.init.shared.b64 [%0], %1;" :: "r"(mb), "r"(4) : "memory");
    if (tid < 16) bmap_s[tid] = 0;   // init both buffers' maps
    __syncthreads();
    asm volatile("barrier.cluster.arrive.aligned;" ::: "memory");
    asm volatile("barrier.cluster.wait.aligned;" ::: "memory");

    // leafW for nonlin roles (b, jj)
    float lw5[5];
#pragma unroll
    for (int g = 0; g < 5; g++) lw5[g] = 0.0f;
    for (int k = 0; k < 128; k++) {
        float lv = leaf_s[k];
#pragma unroll
        for (int g = 0; g < 5; g++)
            lw5[g] += lv * (W_T[(jj * 5 + g) * WROW + k]
                          + W_T[(jj * 5 + g) * WROW + 128 + k]);
    }

    // schedule regs: invariant at top of step t:
    //  csA = slot(t,b), csB = slot(t+1,b), mA = cnt(t), mB = cnt(t+1)
    int csA  = __ldg(&g_cslot[B + b]);
    int csB  = __ldg(&g_cslot[NBAT + B + b]);
    int mA   = __ldg(&g_cnt[cl]);
    int mB   = __ldg(&g_cnt[32 + cl]);
    int liB  = __ldg(&g_lidx[NBAT + B + b]);
    int labB = __ldg(&labels[NBAT + B + b]);
    float tab5[5];
    {
        int labA = __ldg(&labels[B + b]);
#pragma unroll
        for (int g = 0; g < 5; g++)
            tab5[g] = __ldg(&g_table[(size_t)labA * G5 + g * H + r32 + jj]);
    }
    float cl_c = leaf_s[r32 + jj];   // c_left for step t
    float cprev = 0.0f;
    int cur = 0;

    for (int t = 0; t < D; t++) {
        const int nxt = cur ^ 1;

        float cln = 0.0f, t5n[5];
        int csC = 0, mC = 0, liC = 0, labC = 0;
        int li2 = -1, cs2n = -1;
        if (t < D - 1) {
            bool redB = (liB >= 0);
            cln = redB
                ? ((liB == t - 1) ? cprev
                   : __ldcg(&g_cst[(size_t)liB * NH + (B + b) * H + r32 + jj]))
                : leaf_s[r32 + jj];
#pragma unroll
            for (int g = 0; g < 5; g++)
                t5n[g] = __ldg(&g_table[(size_t)labB * G5 + g * H + r32 + jj]);
            const int t2 = (t + 2 < D) ? (t + 2) : (D - 1);
            csC  = __ldg(&g_cslot[t2 * NBAT + B + b]);
            mC   = __ldg(&g_cnt[t2 * 32 + cl]);
            liC  = __ldg(&g_lidx[t2 * NBAT + B + b]);
            labC = __ldg(&labels[t2 * NBAT + B + b]);

            // bmap for step t+1 (buffer nxt): slot -> batch
            if (jj == 0 && csB >= 0) bmap_s[nxt * 8 + csB] = b;

            // cp.async for Xs[next] slot rows (global path only)
            li2  = __ldg(&g_lidx[(t + 1) * NBAT + B + b2]);
            cs2n = __ldg(&g_cslot[(t + 1) * NBAT + B + b2]);
            if (li2 >= 0 && li2 != t - 1) {
                uint32_t dst = (uint32_t)__cvta_generic_to_shared(
                    &Xs[nxt * XBUF + cs2n * XR + s2 * 4]);
                const float* src = &g_hst[(size_t)li2 * NH + (B + b2) * H + s2 * 4];
                asm volatile("cp.async.cg.shared.global [%0], [%1], 16;"
                             :: "r"(dst), "l"(src) : "memory");
            }
            asm volatile("cp.async.commit_group;" ::: "memory");
        }

        // ---- GEMM accumulators ----
        const bool act = (bgq * 4) < mA;
        unsigned long long acc[4][5];
#pragma unroll
        for (int i = 0; i < 4; i++)
#pragma unroll
            for (int g = 0; g < 5; g++) acc[i][g] = 0ULL;

        const ulonglong2* wp =
            reinterpret_cast<const ulonglong2*>(W_T + (jg * 5) * WROW + ks * 64);

        // ---- LEFT half (ks<2, k<128): compacted slots, valid at loop top ----
        if (act && ks < 2) {
            const float* xs = Xs + cur * XBUF + ks * 64;
#pragma unroll 4
            for (int p = 0; p < 16; p++) {
                ulonglong2 xv[4];
#pragma unroll
                for (int i = 0; i < 4; i++)
                    xv[i] = *reinterpret_cast<const ulonglong2*>(
                        xs + (bgq * 4 + i) * XR + p * 4);
#pragma unroll
                for (int g = 0; g < 5; g++) {
                    ulonglong2 wv = wp[g * 65 + p];
#pragma unroll
                    for (int i = 0; i < 4; i++) {
                        asm("fma.rn.f32x2 %0, %1, %2, %0;"
                            : "+l"(acc[i][g]) : "l"(xv[i].x), "l"(wv.x));
                        asm("fma.rn.f32x2 %0, %1, %2, %0;"
                            : "+l"(acc[i][g]) : "l"(xv[i].y), "l"(wv.y));
                    }
                }
            }
        }

        // ---- deferred handshake wait (h(t-1) pushes into hprev[cur]) ----
        if (t > 0) {
            const unsigned par = (t - 1) & 1;
            asm volatile(
                "{\n\t"
                ".reg .pred P;\n\t"
                "WL%=:\n\t"
                "mbarrier.try_wait.parity.acquire.cluster.shared::cta.b64 P, [%0], %1, 0x989680;\n\t"
                "@P bra WD%=;\n\t"
                "bra WL%=;\n\t"
                "WD%=:\n\t"
                "}" :: "r"(mb), "r"(par) : "memory");
        }

        // local copy: Xs[next] slot <- hprev[cur] (left child == t-1)
        if (li2 == t - 1 && li2 >= 0) {
            float4 v = *reinterpret_cast<const float4*>(
                &hprev[cur * XBUF + b2 * XR + s2 * 4]);
            *reinterpret_cast<float4*>(
                &Xs[nxt * XBUF + cs2n * XR + s2 * 4]) = v;
        }

        // ---- RIGHT half (ks>=2, k>=128): hprev[cur] via slot->batch map ----
        if (act && ks >= 2) {
            int bb[4];
#pragma unroll
            for (int i = 0; i < 4; i++) {
                int slot = bgq * 4 + i;
                bb[i] = (slot < mA) ? bmap_s[cur * 8 + slot] : 0;  // clamp dead slots
            }
            const float* hp = hprev + cur * XBUF + (ks - 2) * 64;
#pragma unroll 4
            for (int p = 0; p < 16; p++) {
                ulonglong2 xv[4];
#pragma unroll
                for (int i = 0; i < 4; i++)
                    xv[i] = *reinterpret_cast<const ulonglong2*>(
                        hp + bb[i] * XR + p * 4);
#pragma unroll
                for (int g = 0; g < 5; g++) {
                    ulonglong2 wv = wp[g * 65 + p];
#pragma unroll
                    for (int i = 0; i < 4; i++) {
                        asm("fma.rn.f32x2 %0, %1, %2, %0;"
                            : "+l"(acc[i][g]) : "l"(xv[i].x), "l"(wv.x));
                        asm("fma.rn.f32x2 %0, %1, %2, %0;"
                            : "+l"(acc[i][g]) : "l"(xv[i].y), "l"(wv.y));
                    }
                }
            }
        }

        // partials -> Gp (slot-indexed)
        if (act) {
#pragma unroll
            for (int g = 0; g < 5; g++)
#pragma unroll
                for (int i = 0; i < 4; i++)
                    *reinterpret_cast<unsigned long long*>(
                        &Gp[(jg * 5 + g) * GPR + ks * 16 + (bgq * 4 + i) * 2]) = acc[i][g];
        }
        __syncthreads();   // (1)

        // ---- reduce + nonlinearity + push: thread owns (b, jj) ----
        {
            float gate[5];
            if (csA >= 0) {
#pragma unroll
                for (int g = 0; g < 5; g++) {
                    float s = tab5[g];
#pragma unroll
                    for (int q2 = 0; q2 < 4; q2++) {
                        unsigned long long pv = *reinterpret_cast<unsigned long long*>(
                            &Gp[(jj * 5 + g) * GPR + q2 * 16 + csA * 2]);
                        s += ull_lo(pv) + ull_hi(pv);
                    }
                    gate[g] = s;
                }
            } else {
#pragma unroll
                for (int g = 0; g < 5; g++) gate[g] = tab5[g] + lw5[g];
            }
            float lf  = leaf_s[r32 + jj];
            float clv = (csA >= 0) ? cl_c  : lf;
            float crv = (csA >= 0) ? cprev : lf;
            float c = sigf(gate[0]) * tanhfast(gate[4])
                    + sigf(gate[1]) * clv + sigf(gate[2]) * crv;
            float h = sigf(gate[3]) * tanhfast(c);
            cprev = c;
            hstage[b * HSROW + jj] = h;
            cstage[b * HSROW + jj] = c;
            // unconditional push of h into all 4 CTAs' hprev[next]
            if (t < D - 1) {
                uint32_t xaddr = hpb + (nxt * XBUF + b * XR + r32 + jj) * 4;
#pragma unroll
                for (int cta = 0; cta < 4; cta++) {
                    uint32_t rem;
                    asm("mapa.shared::cluster.u32 %0, %1, %2;"
                        : "=r"(rem) : "r"(xaddr), "r"(cta));
                    asm volatile("st.shared::cluster.f32 [%0], %1;"
                                 :: "r"(rem), "f"(h) : "memory");
                }
            }
        }

        // cp.async completion BEFORE the barrier that releases readers
        if (t < D - 1)
            asm volatile("cp.async.wait_group 0;" ::: "memory");
        __syncthreads();   // (2)

        // ---- release arrive ASAP ----
        if (t < D - 1 && tid < 4) {
            uint32_t rem;
            asm("mapa.shared::cluster.u32 %0, %1, %2;"
                : "=r"(rem) : "r"(mb), "r"(tid));
            asm volatile("mbarrier.arrive.release.cluster.shared::cluster.b64 _, [%0];"
                         :: "r"(rem) : "memory");
        }

        // ---- writeback AFTER arrive ----
        {
            float hv = hstage[b2 * HSROW + s2];
            float cv = cstage[b2 * HSROW + s2];
            const size_t o = (size_t)t * NH + (B + b2) * H + r32 + s2;
            __stcg(&g_hst[o], hv);
            __stcg(&g_cst[o], cv);
            if (t == D - 1) {
                out[(B + b2) * H + r32 + s2]      = cv;   // cells
                out[NH + (B + b2) * H + r32 + s2] = hv;   // embeddings
            }
        }

        csA = csB; csB = csC; mA = mB; mB = mC;
        liB = liC; labB = labC;
        cl_c = cln;
#pragma unroll
        for (int g = 0; g < 5; g++) tab5[g] = t5n[g];
        cur ^= 1;
    }

    asm volatile("barrier.cluster.arrive.aligned;" ::: "memory");
    asm volatile("barrier.cluster.wait.aligned;" ::: "memory");
}

// ============================================================
extern "C" void kernel_launch(void* const* d_in, const int* in_sizes, int n_in,
                              void* d_out, int out_size) {
    const int*   trans  = (const int*)d_in[0];
    const int*   labels = (const int*)d_in[1];
    const float* emb    = (const float*)d_in[2];
    const float* W      = (const float*)d_in[3];
    const float* bias   = (const float*)d_in[4];
    const float* leaf   = (const float*)d_in[5];
    float* out = (float*)d_out;

    cudaFuncSetAttribute(k_pre, cudaFuncAttributeMaxDynamicSharedMemorySize,
                         64 * 33 * 4 + 64 * 160 * 4);
    cudaFuncSetAttribute(k_main, cudaFuncAttributeMaxDynamicSharedMemorySize,
                         SM_TOT);

    dim3 pgrid(NV / 32, 5);
    k_pre<<<pgrid, 256, 64 * 33 * 4 + 64 * 160 * 4>>>(emb, W, bias, trans);
    k_main<<<148, 256, SM_TOT>>>(labels, W, leaf, out);
}